// round 12
// baseline (speedup 1.0000x reference)
#include <cuda_runtime.h>
#include <cstdint>

#define T_SEQ 1024
#define BATCH 256
#define ISZ   128
#define HSZ   64
#define GSZ   256   // 4*H
#define NBP   128   // BATCH/2 (batch pairs)
#define NBG   32    // BATCH/8 (batch groups of 8 for mma n=8)
#define NCLS  10

typedef unsigned long long ull;

// Scratch (device globals — allocation-free per harness rules)
// Layout: [t][bp][g] of float2{batch 2bp, batch 2bp+1}
__device__ float2 g_xproj[(size_t)T_SEQ * NBP * GSZ];   // 268 MB
__device__ ull    g_hT[NBP * HSZ];                      // final hidden, packed pairs

// ---------- helpers ----------
union F2U { float2 f2; ull u; };

__device__ __forceinline__ ull pack2(float lo, float hi) {
    F2U t; t.f2 = make_float2(lo, hi); return t.u;
}
__device__ __forceinline__ float2 unpack2(ull v) {
    F2U t; t.u = v; return t.f2;
}
__device__ __forceinline__ unsigned f2tf32(float f) {
    unsigned r;
    asm("cvt.rna.tf32.f32 %0, %1;" : "=r"(r) : "f"(f));
    return r;
}
__device__ __forceinline__ float ex2_ap(float x) {
    float y; asm("ex2.approx.f32 %0, %1;" : "=f"(y) : "f"(x)); return y;
}
__device__ __forceinline__ float rcp_ap(float x) {
    float y; asm("rcp.approx.f32 %0, %1;" : "=f"(y) : "f"(x)); return y;
}
// tanh(x) = 1 - 2/(1+2^(2x*log2e)) : branch-free
__device__ __forceinline__ float tanh_f(float x) {
    return fmaf(-2.0f, rcp_ap(1.0f + ex2_ap(2.8853900817779268f * x)), 1.0f);
}

#define MMA_TF32(D, A, B)                                              \
    asm volatile(                                                      \
        "mma.sync.aligned.m16n8k8.row.col.f32.tf32.tf32.f32 "          \
        "{%0,%1,%2,%3}, {%4,%5,%6,%7}, {%8,%9}, {%0,%1,%2,%3};"        \
        : "+f"((D)[0]), "+f"((D)[1]), "+f"((D)[2]), "+f"((D)[3])       \
        : "r"((A)[0]), "r"((A)[1]), "r"((A)[2]), "r"((A)[3]),          \
          "r"((B)[0]), "r"((B)[1]))

// =====================================================================
// Kernel A: x_proj — EXACT round-1 version (measured 207-208us, 96 regs).
// =====================================================================
__global__ __launch_bounds__(128) void xproj_kernel(
    const float* __restrict__ x, const float* __restrict__ W_ih,
    const float* __restrict__ b_ih, const float* __restrict__ b_hh)
{
    __shared__ float As[2][16][68];
    __shared__ float Ws[128][68];
    __shared__ float bias_s[128];

    const int tid  = threadIdx.x;
    const int warp = tid >> 5, lane = tid & 31;
    const int gid  = lane >> 2, tig = lane & 3;
    const int gbase = blockIdx.x * 128;
    const int t0    = blockIdx.y * 16;
    const int bp    = blockIdx.z;
    const int b0g   = bp * 2;

    bias_s[tid] = b_ih[gbase + tid] + b_hh[gbase + tid];

    float acc[2][4][4];
    #pragma unroll
    for (int b = 0; b < 2; b++)
        #pragma unroll
        for (int n = 0; n < 4; n++)
            #pragma unroll
            for (int i = 0; i < 4; i++) acc[b][n][i] = 0.f;

    for (int kc = 0; kc < 128; kc += 64) {
        #pragma unroll
        for (int r = 0; r < 4; ++r) {
            int idx = tid + r * 128;
            int b   = idx >> 8;
            int rem = idx & 255;
            int tt  = rem >> 4;
            int v   = rem & 15;
            float4 src = *(const float4*)&x[(((size_t)(b0g + b)) * T_SEQ + (t0 + tt)) * ISZ + kc + v * 4];
            *(float4*)&As[b][tt][v * 4] = src;
        }
        #pragma unroll
        for (int r = 0; r < 16; ++r) {
            int idx = tid + r * 128;
            int gg  = idx >> 4;
            int v   = idx & 15;
            float4 src = *(const float4*)&W_ih[((size_t)(gbase + gg)) * ISZ + kc + v * 4];
            *(float4*)&Ws[gg][v * 4] = src;
        }
        __syncthreads();

        #pragma unroll
        for (int ks = 0; ks < 8; ++ks) {
            const int k0 = ks * 8;
            unsigned a[2][4];
            #pragma unroll
            for (int b = 0; b < 2; b++) {
                a[b][0] = f2tf32(As[b][gid    ][k0 + tig]);
                a[b][1] = f2tf32(As[b][gid + 8][k0 + tig]);
                a[b][2] = f2tf32(As[b][gid    ][k0 + tig + 4]);
                a[b][3] = f2tf32(As[b][gid + 8][k0 + tig + 4]);
            }
            #pragma unroll
            for (int nt = 0; nt < 4; nt++) {
                const int nl = warp * 32 + nt * 8 + gid;
                unsigned bb[2];
                bb[0] = f2tf32(Ws[nl][k0 + tig]);
                bb[1] = f2tf32(Ws[nl][k0 + tig + 4]);
                #pragma unroll
                for (int b = 0; b < 2; b++) MMA_TF32(acc[b][nt], a[b], bb);
            }
        }
        __syncthreads();
    }

    #pragma unroll
    for (int nt = 0; nt < 4; nt++) {
        const int nl  = warp * 32 + nt * 8 + 2 * tig;
        const float bs0 = bias_s[nl], bs1 = bias_s[nl + 1];
        const int ggl = gbase + nl;
        const int tr0 = t0 + gid, tr1 = t0 + gid + 8;
        float4 v0 = make_float4(acc[0][nt][0] + bs0, acc[1][nt][0] + bs0,
                                acc[0][nt][1] + bs1, acc[1][nt][1] + bs1);
        float4 v1 = make_float4(acc[0][nt][2] + bs0, acc[1][nt][2] + bs0,
                                acc[0][nt][3] + bs1, acc[1][nt][3] + bs1);
        *(float4*)&g_xproj[((size_t)tr0 * NBP + bp) * GSZ + ggl] = v0;
        *(float4*)&g_xproj[((size_t)tr1 * NBP + bp) * GSZ + ggl] = v1;
    }
}

// =====================================================================
// Kernel B: recurrence on TENSOR CORES. 32 CTAs x 8 batches, 256 thr.
// Per step: G[256x8] = W_hh[256x64] @ h[64x8] + xp  via m16n8k8 tf32.
// A frags (W_hh) static in 64 regs/thread. B frags = h (tf32 bits in
// SMEM, written by tail). D init = xp loads straight from g_xproj
// (the [t][bp][g]float2 layout matches the D-frag col pairing).
// Warp w owns gate rows [32w,32w+32) -> warp-uniform activation.
// =====================================================================
__global__ __launch_bounds__(256, 1) void lstm_mma_kernel(const float* __restrict__ W_hh)
{
    __shared__ unsigned h_bits[HSZ][8];   // tf32 bits of h [k][batch-in-group]
    __shared__ float    gate_s[GSZ][8];   // activated gates [row][batch]

    const int tid  = threadIdx.x;
    const int w    = tid >> 5, lane = tid & 31;
    const int gid  = lane >> 2, tig = lane & 3;
    const int bg   = blockIdx.x;          // batch group: batches 8bg..8bg+7
    const int mbase = w * 32;             // this warp's gate-row base
    const int sec  = w >> 1;              // 0:i 1:f 2:g 3:o (warp-uniform)

    // branch-free activation constants: r = aco * sigm(kmul*x) + bco
    const float kmul = (sec == 2) ? 2.8853900817779268f : 1.4426950408889634f;
    const float aco  = (sec == 2) ?  2.0f : 1.0f;
    const float bco  = (sec == 2) ? -1.0f : 0.0f;

    // ---- static A fragments: W_hh rows [mbase, mbase+32), tf32 ----
    unsigned afr[2][8][4];
    #pragma unroll
    for (int mt = 0; mt < 2; ++mt) {
        const int r0 = mbase + mt * 16 + gid;
        #pragma unroll
        for (int kc = 0; kc < 8; ++kc) {
            const int k0 = kc * 8 + tig;
            afr[mt][kc][0] = f2tf32(W_hh[(r0    ) * HSZ + k0    ]);
            afr[mt][kc][1] = f2tf32(W_hh[(r0 + 8) * HSZ + k0    ]);
            afr[mt][kc][2] = f2tf32(W_hh[(r0    ) * HSZ + k0 + 4]);
            afr[mt][kc][3] = f2tf32(W_hh[(r0 + 8) * HSZ + k0 + 4]);
        }
    }

    // zero h (tf32 bits of 0.0f are 0)
    ((uint2*)h_bits)[tid] = make_uint2(0u, 0u);

    // tail ownership: thread -> (j = tid>>2, batches tb, tb+1)
    const int tj = tid >> 2;
    const int tb = (tid & 3) * 2;
    float c0 = 0.f, c1 = 0.f;
    __syncthreads();

    // xp addressing: col pair (2tig,2tig+1) lives at bp = bg*4+tig
    const float2* xp = g_xproj;
    const size_t bpoff = (size_t)(bg * 4 + tig) * GSZ;
    const int r0 = mbase + gid;           // rows per (mt, half): r0, r0+8, r0+16, r0+24
    // prefetch xp for t=0,1 (4 float2 each: [mt0 lo, mt0 hi, mt1 lo, mt1 hi])
    float2 xC[4], xN[4];
    #pragma unroll
    for (int q = 0; q < 4; ++q) {
        xC[q] = xp[bpoff + r0 + (q >> 1) * 16 + (q & 1) * 8];
        xN[q] = xp[(size_t)NBP * GSZ + bpoff + r0 + (q >> 1) * 16 + (q & 1) * 8];
    }

    for (int t = 0; t < T_SEQ; ++t) {
        // prefetch t+2 (clamped)
        const size_t toff = (size_t)((t + 2 < T_SEQ) ? t + 2 : T_SEQ - 1) * (NBP * GSZ);
        float2 xP[4];
        #pragma unroll
        for (int q = 0; q < 4; ++q)
            xP[q] = xp[toff + bpoff + r0 + (q >> 1) * 16 + (q & 1) * 8];

        // B fragments from h (conflict-free LDS.32)
        unsigned bfr[8][2];
        #pragma unroll
        for (int kc = 0; kc < 8; ++kc) {
            bfr[kc][0] = h_bits[kc * 8 + tig    ][gid];
            bfr[kc][1] = h_bits[kc * 8 + tig + 4][gid];
        }

        // D init from xp, then 16 mma (2 m-tiles x 8 k-chunks)
        float d0[4] = {xC[0].x, xC[0].y, xC[1].x, xC[1].y};
        float d1[4] = {xC[2].x, xC[2].y, xC[3].x, xC[3].y};
        #pragma unroll
        for (int kc = 0; kc < 8; ++kc) {
            MMA_TF32(d0, afr[0][kc], bfr[kc]);
            MMA_TF32(d1, afr[1][kc], bfr[kc]);
        }
        #pragma unroll
        for (int q = 0; q < 4; ++q) { xC[q] = xN[q]; xN[q] = xP[q]; }

        // warp-uniform branch-free activation on all 8 values
        #pragma unroll
        for (int i = 0; i < 4; ++i) {
            d0[i] = fmaf(aco, rcp_ap(1.0f + ex2_ap(-kmul * d0[i])), bco);
            d1[i] = fmaf(aco, rcp_ap(1.0f + ex2_ap(-kmul * d1[i])), bco);
        }

        // store activated gates: rows (gid, gid+8) x2 m-tiles, cols 2tig..+1
        *(float2*)&gate_s[mbase + gid     ][2 * tig] = make_float2(d0[0], d0[1]);
        *(float2*)&gate_s[mbase + gid + 8 ][2 * tig] = make_float2(d0[2], d0[3]);
        *(float2*)&gate_s[mbase + gid + 16][2 * tig] = make_float2(d1[0], d1[1]);
        *(float2*)&gate_s[mbase + gid + 24][2 * tig] = make_float2(d1[2], d1[3]);
        __syncthreads();

        // tail: all 256 threads, one (j, batch-pair) each
        {
            float2 iv = *(const float2*)&gate_s[      tj][tb];
            float2 fv = *(const float2*)&gate_s[ 64 + tj][tb];
            float2 gg = *(const float2*)&gate_s[128 + tj][tb];
            float2 ov = *(const float2*)&gate_s[192 + tj][tb];
            c0 = fmaf(fv.x, c0, iv.x * gg.x);
            c1 = fmaf(fv.y, c1, iv.y * gg.y);
            float h0 = ov.x * tanh_f(c0);
            float h1 = ov.y * tanh_f(c1);
            *(uint2*)&h_bits[tj][tb] = make_uint2(f2tf32(h0), f2tf32(h1));
            if (t == T_SEQ - 1)
                g_hT[(bg * 4 + (tid & 3)) * HSZ + tj] = pack2(h0, h1);
        }
        __syncthreads();
    }
}

// =====================================================================
// Kernel C: logits = h_T @ W_cls^T + b_cls   (256 x 10)
// =====================================================================
__global__ void cls_kernel(const float* __restrict__ W_cls,
                           const float* __restrict__ b_cls,
                           float* __restrict__ out)
{
    const int b = blockIdx.x, lane = threadIdx.x;
    const int bp = b >> 1, par = b & 1;
    float2 p0 = unpack2(g_hT[bp * HSZ + lane]);
    float2 p1 = unpack2(g_hT[bp * HSZ + lane + 32]);
    float h0 = par ? p0.y : p0.x;
    float h1 = par ? p1.y : p1.x;
    #pragma unroll
    for (int c = 0; c < NCLS; ++c) {
        float p = h0 * W_cls[c * HSZ + lane] + h1 * W_cls[c * HSZ + lane + 32];
        #pragma unroll
        for (int off = 16; off; off >>= 1)
            p += __shfl_xor_sync(0xffffffffu, p, off);
        if (lane == 0) out[b * NCLS + c] = p + b_cls[c];
    }
}

// =====================================================================
extern "C" void kernel_launch(void* const* d_in, const int* in_sizes, int n_in,
                              void* d_out, int out_size) {
    const float* x     = (const float*)d_in[0];
    const float* W_ih  = (const float*)d_in[1];
    const float* W_hh  = (const float*)d_in[2];
    const float* b_ih  = (const float*)d_in[3];
    const float* b_hh  = (const float*)d_in[4];
    const float* W_cls = (const float*)d_in[5];
    const float* b_cls = (const float*)d_in[6];
    float* out = (float*)d_out;

    dim3 gA(2, 64, 128);               // g-tiles x t-tiles x batch-pairs
    xproj_kernel<<<gA, 128>>>(x, W_ih, b_ih, b_hh);
    lstm_mma_kernel<<<NBG, 256>>>(W_hh);
    cls_kernel<<<BATCH, 32>>>(W_cls, b_cls, out);
}

// round 15
// speedup vs baseline: 1.4348x; 1.4348x over previous
#include <cuda_runtime.h>
#include <cstdint>

#define T_SEQ 1024
#define BATCH 256
#define ISZ   128
#define HSZ   64
#define GSZ   256   // 4*H
#define NBP   128   // BATCH/2 (batch pairs)
#define NCLS  10
#define NGRP  128   // T_SEQ/8 groups
#define WPITCH 132  // padded k-pitch (words) for conflict-free frag LDS
#define RPITCH 260  // ring row pitch in float2 units

typedef unsigned long long ull;

// final hidden, packed pairs (cls kernel input)
__device__ ull g_hT[NBP * HSZ];

// ---------- helpers ----------
union F2U { float2 f2; ull u; };

__device__ __forceinline__ ull pack2(float lo, float hi) {
    F2U t; t.f2 = make_float2(lo, hi); return t.u;
}
__device__ __forceinline__ float2 unpack2(ull v) {
    F2U t; t.u = v; return t.f2;
}
__device__ __forceinline__ ull ffma2(ull a, ull b, ull c) {
    ull d;
    asm("fma.rn.f32x2 %0, %1, %2, %3;" : "=l"(d) : "l"(a), "l"(b), "l"(c));
    return d;
}
__device__ __forceinline__ ull fadd2(ull a, ull b) {
    ull d;
    asm("add.rn.f32x2 %0, %1, %2;" : "=l"(d) : "l"(a), "l"(b));
    return d;
}
__device__ __forceinline__ unsigned f2tf32(float f) {
    unsigned r;
    asm("cvt.rna.tf32.f32 %0, %1;" : "=r"(r) : "f"(f));
    return r;
}
__device__ __forceinline__ float ex2_ap(float x) {
    float y; asm("ex2.approx.f32 %0, %1;" : "=f"(y) : "f"(x)); return y;
}
__device__ __forceinline__ float rcp_ap(float x) {
    float y; asm("rcp.approx.f32 %0, %1;" : "=f"(y) : "f"(x)); return y;
}
// tanh(x) = 1 - 2/(1+2^(2x*log2e)) : branch-free
__device__ __forceinline__ float tanh_f(float x) {
    return fmaf(-2.0f, rcp_ap(1.0f + ex2_ap(2.8853900817779268f * x)), 1.0f);
}

#define MMA_TF32(D, A0, A1, A2, A3, B0, B1)                            \
    asm volatile(                                                      \
        "mma.sync.aligned.m16n8k8.row.col.f32.tf32.tf32.f32 "          \
        "{%0,%1,%2,%3}, {%4,%5,%6,%7}, {%8,%9}, {%0,%1,%2,%3};"        \
        : "+f"((D)[0]), "+f"((D)[1]), "+f"((D)[2]), "+f"((D)[3])       \
        : "r"(A0), "r"(A1), "r"(A2), "r"(A3), "r"(B0), "r"(B1))

// =====================================================================
// FUSED kernel: 128 CTAs (one batch pair), 256 threads, persistent.
// Per 8-step group: produce x_proj for the group's 8 timesteps on the
// TENSOR pipe ([16 rows=(2b x 8t)] x [256 g] x [128 k], R1-proven frag
// layout), then run 8 recurrence steps (R11-proven FFMA2 loop) consuming
// the SMEM ring. W_ih lives in SMEM (tf32); x is LDG-prefetched one
// group ahead. No x_proj global traffic at all.
// =====================================================================
__global__ __launch_bounds__(256, 1) void lstm_fused_kernel(
    const float* __restrict__ x, const float* __restrict__ W_ih,
    const float* __restrict__ W_hh,
    const float* __restrict__ b_ih, const float* __restrict__ b_hh)
{
    extern __shared__ __align__(16) unsigned smem_raw[];
    unsigned* Wst  = smem_raw;                       // 256*132 tf32 words
    unsigned* Ast  = Wst + GSZ * WPITCH;             // 16*132 tf32 words
    float*    ring = (float*)(Ast + 16 * WPITCH);    // 8 * RPITCH * 2 floats
    ull*      h_s  = (ull*)(ring + 8 * RPITCH * 2);  // 64
    ull*      gate_s = h_s + HSZ;                    // 256

    const int tid  = threadIdx.x;
    const int warp = tid >> 5, lane = tid & 31;
    const int gid  = lane >> 2, tig = lane & 3;
    const int bp   = blockIdx.x;
    const int b0g  = bp * 2;

    const int g   = tid;              // gate row for recurrence
    const int j   = g & 63;
    const int sec = g >> 6;           // 0:i 1:f 2:g 3:o (warp-uniform)
    const float kmul = (sec == 2) ? 2.8853900817779268f : 1.4426950408889634f;
    const float aco  = (sec == 2) ?  2.0f : 1.0f;
    const float bco  = (sec == 2) ? -1.0f : 0.0f;

    // bias folded into the step
    const float bsum = b_ih[g] + b_hh[g];
    const ull bias2 = pack2(bsum, bsum);

    // ---- W_hh row g duplicated into f32x2 pairs (128 regs) ----
    ull w2[HSZ];
    {
        const float4* wrow = (const float4*)&W_hh[g * HSZ];
        #pragma unroll
        for (int q = 0; q < 16; ++q) {
            float4 w = wrow[q];
            w2[q * 4 + 0] = pack2(w.x, w.x);
            w2[q * 4 + 1] = pack2(w.y, w.y);
            w2[q * 4 + 2] = pack2(w.z, w.z);
            w2[q * 4 + 3] = pack2(w.w, w.w);
        }
    }

    // ---- stage W_ih -> SMEM as tf32, [g][k] pitch WPITCH ----
    for (int i = tid; i < GSZ * (ISZ / 4); i += 256) {
        int gg = i >> 5, s = i & 31;
        float4 v = ((const float4*)W_ih)[(size_t)gg * 32 + s];
        unsigned* dst = &Wst[gg * WPITCH + s * 4];
        dst[0] = f2tf32(v.x); dst[1] = f2tf32(v.y);
        dst[2] = f2tf32(v.z); dst[3] = f2tf32(v.w);
    }
    if (tid < HSZ) h_s[tid] = 0ull;

    // ---- fetch x for group 0 (row = b*8+tl, 8 floats per thread) ----
    const int xrow = tid >> 4;        // 0..15
    const int xseg = tid & 15;        // k = 8*xseg
    const int xb   = xrow >> 3, xtl = xrow & 7;
    const size_t xbase = (((size_t)(b0g + xb)) * T_SEQ + xtl) * ISZ + xseg * 8;
    float4 xr0 = *(const float4*)&x[xbase];
    float4 xr1 = *(const float4*)&x[xbase + 4];

    float c0 = 0.f, c1 = 0.f;

    for (int P = 0; P < NGRP; ++P) {
        // ---- stage x group P into Ast (tf32) ----
        {
            unsigned* dst = &Ast[xrow * WPITCH + xseg * 8];
            dst[0] = f2tf32(xr0.x); dst[1] = f2tf32(xr0.y);
            dst[2] = f2tf32(xr0.z); dst[3] = f2tf32(xr0.w);
            dst[4] = f2tf32(xr1.x); dst[5] = f2tf32(xr1.y);
            dst[6] = f2tf32(xr1.z); dst[7] = f2tf32(xr1.w);
        }
        __syncthreads();

        // ---- prefetch x for group P+1 (latency hidden by produce+steps) ----
        if (P + 1 < NGRP) {
            const size_t nb = xbase + (size_t)(P + 1) * 8 * ISZ;
            xr0 = *(const float4*)&x[nb];
            xr1 = *(const float4*)&x[nb + 4];
        }

        // ---- produce: gates preact for this group's 8 steps ----
        {
            float acc[4][4];
            #pragma unroll
            for (int n = 0; n < 4; n++)
                #pragma unroll
                for (int i = 0; i < 4; i++) acc[n][i] = 0.f;

            #pragma unroll
            for (int ks = 0; ks < 16; ++ks) {
                const int k0 = ks * 8;
                unsigned a0 = Ast[ gid      * WPITCH + k0 + tig];
                unsigned a1 = Ast[(gid + 8) * WPITCH + k0 + tig];
                unsigned a2 = Ast[ gid      * WPITCH + k0 + tig + 4];
                unsigned a3 = Ast[(gid + 8) * WPITCH + k0 + tig + 4];
                #pragma unroll
                for (int nt = 0; nt < 4; nt++) {
                    const int nl = warp * 32 + nt * 8 + gid;
                    unsigned bb0 = Wst[nl * WPITCH + k0 + tig];
                    unsigned bb1 = Wst[nl * WPITCH + k0 + tig + 4];
                    MMA_TF32(acc[nt], a0, a1, a2, a3, bb0, bb1);
                }
            }
            // D rows: gid -> (b0, tl=gid), gid+8 -> (b1, tl=gid); cols 2tig,2tig+1
            #pragma unroll
            for (int nt = 0; nt < 4; nt++) {
                const int nl2 = warp * 32 + nt * 8 + 2 * tig;
                float* r0 = &ring[(gid * RPITCH + nl2) * 2];
                r0[0] = acc[nt][0];      // (b0, col nl2)
                r0[2] = acc[nt][1];      // (b0, col nl2+1)
                r0[1] = acc[nt][2];      // (b1, col nl2)
                r0[3] = acc[nt][3];      // (b1, col nl2+1)
            }
        }
        __syncthreads();

        // ---- 8 recurrence steps (R11-proven body; xp from SMEM ring) ----
        for (int tl = 0; tl < 8; ++tl) {
            ull xp = *(ull*)&ring[(tl * RPITCH + g) * 2];

            ull acc0 = 0ull, acc1 = 0ull, acc2 = 0ull, acc3 = 0ull;
            const ulonglong2* h2 = (const ulonglong2*)h_s;
            #pragma unroll
            for (int kk = 0; kk < 16; ++kk) {
                ulonglong2 ha = h2[2 * kk];
                ulonglong2 hb = h2[2 * kk + 1];
                acc0 = ffma2(w2[4 * kk + 0], ha.x, acc0);
                acc1 = ffma2(w2[4 * kk + 1], ha.y, acc1);
                acc2 = ffma2(w2[4 * kk + 2], hb.x, acc2);
                acc3 = ffma2(w2[4 * kk + 3], hb.y, acc3);
            }
            ull gsum = fadd2(fadd2(acc0, acc1), fadd2(acc2, acc3));
            gsum = fadd2(gsum, fadd2(xp, bias2));

            float2 gv = unpack2(gsum);
            float r0 = fmaf(aco, rcp_ap(1.0f + ex2_ap(-kmul * gv.x)), bco);
            float r1 = fmaf(aco, rcp_ap(1.0f + ex2_ap(-kmul * gv.y)), bco);
            gate_s[g] = pack2(r0, r1);
            __syncthreads();

            if (g < HSZ) {
                float2 iv = unpack2(gate_s[j]);
                float2 fv = unpack2(gate_s[64 + j]);
                float2 gg = unpack2(gate_s[128 + j]);
                float2 ov = unpack2(gate_s[192 + j]);
                c0 = fmaf(fv.x, c0, iv.x * gg.x);
                c1 = fmaf(fv.y, c1, iv.y * gg.y);
                float h0 = ov.x * tanh_f(c0);
                float h1 = ov.y * tanh_f(c1);
                ull hp = pack2(h0, h1);
                h_s[j] = hp;
                if (P == NGRP - 1 && tl == 7) g_hT[bp * HSZ + j] = hp;
            }
            __syncthreads();
        }
    }
}

// =====================================================================
// Kernel C: logits = h_T @ W_cls^T + b_cls   (256 x 10)
// =====================================================================
__global__ void cls_kernel(const float* __restrict__ W_cls,
                           const float* __restrict__ b_cls,
                           float* __restrict__ out)
{
    const int b = blockIdx.x, lane = threadIdx.x;
    const int bp = b >> 1, par = b & 1;
    float2 p0 = unpack2(g_hT[bp * HSZ + lane]);
    float2 p1 = unpack2(g_hT[bp * HSZ + lane + 32]);
    float h0 = par ? p0.y : p0.x;
    float h1 = par ? p1.y : p1.x;
    #pragma unroll
    for (int c = 0; c < NCLS; ++c) {
        float p = h0 * W_cls[c * HSZ + lane] + h1 * W_cls[c * HSZ + lane + 32];
        #pragma unroll
        for (int off = 16; off; off >>= 1)
            p += __shfl_xor_sync(0xffffffffu, p, off);
        if (lane == 0) out[b * NCLS + c] = p + b_cls[c];
    }
}

// =====================================================================
static const int SMEM_BYTES =
    (GSZ * WPITCH + 16 * WPITCH) * 4 +      // Wst + Ast (tf32 words)
    8 * RPITCH * 2 * 4 +                     // ring
    (HSZ + GSZ) * 8;                         // h_s + gate_s (ull)

extern "C" void kernel_launch(void* const* d_in, const int* in_sizes, int n_in,
                              void* d_out, int out_size) {
    const float* x     = (const float*)d_in[0];
    const float* W_ih  = (const float*)d_in[1];
    const float* W_hh  = (const float*)d_in[2];
    const float* b_ih  = (const float*)d_in[3];
    const float* b_hh  = (const float*)d_in[4];
    const float* W_cls = (const float*)d_in[5];
    const float* b_cls = (const float*)d_in[6];
    float* out = (float*)d_out;

    cudaFuncSetAttribute(lstm_fused_kernel,
                         cudaFuncAttributeMaxDynamicSharedMemorySize, SMEM_BYTES);
    lstm_fused_kernel<<<NBP, 256, SMEM_BYTES>>>(x, W_ih, W_hh, b_ih, b_hh);
    cls_kernel<<<BATCH, 32>>>(W_cls, b_cls, out);
}

// round 16
// speedup vs baseline: 1.5806x; 1.1016x over previous
#include <cuda_runtime.h>
#include <cstdint>

#define T_SEQ 1024
#define BATCH 256
#define ISZ   128
#define HSZ   64
#define GSZ   256   // 4*H
#define NBP   128   // BATCH/2 (batch pairs)
#define NCLS  10
#define NGRP  128   // T_SEQ/8 groups
#define WPITCH 132  // padded k-pitch (words) for conflict-free frag LDS
#define RPITCH 260  // ring row pitch in float2 units
#define NTHR  384   // 256 consumer + 128 producer threads

typedef unsigned long long ull;

// final hidden, packed pairs (cls kernel input)
__device__ ull g_hT[NBP * HSZ];

// ---------- helpers ----------
union F2U { float2 f2; ull u; };

__device__ __forceinline__ ull pack2(float lo, float hi) {
    F2U t; t.f2 = make_float2(lo, hi); return t.u;
}
__device__ __forceinline__ float2 unpack2(ull v) {
    F2U t; t.u = v; return t.f2;
}
__device__ __forceinline__ ull ffma2(ull a, ull b, ull c) {
    ull d;
    asm("fma.rn.f32x2 %0, %1, %2, %3;" : "=l"(d) : "l"(a), "l"(b), "l"(c));
    return d;
}
__device__ __forceinline__ ull fadd2(ull a, ull b) {
    ull d;
    asm("add.rn.f32x2 %0, %1, %2;" : "=l"(d) : "l"(a), "l"(b));
    return d;
}
__device__ __forceinline__ unsigned f2tf32(float f) {
    unsigned r;
    asm("cvt.rna.tf32.f32 %0, %1;" : "=r"(r) : "f"(f));
    return r;
}
__device__ __forceinline__ float ex2_ap(float x) {
    float y; asm("ex2.approx.f32 %0, %1;" : "=f"(y) : "f"(x)); return y;
}
__device__ __forceinline__ float rcp_ap(float x) {
    float y; asm("rcp.approx.f32 %0, %1;" : "=f"(y) : "f"(x)); return y;
}
// tanh(x) = 1 - 2/(1+2^(2x*log2e)) : branch-free
__device__ __forceinline__ float tanh_f(float x) {
    return fmaf(-2.0f, rcp_ap(1.0f + ex2_ap(2.8853900817779268f * x)), 1.0f);
}

#define BAR_CONS() asm volatile("bar.sync 1, 256;" ::: "memory")
#define BAR_PROD() asm volatile("bar.sync 3, 128;" ::: "memory")

#define MMA_TF32(D, A0, A1, A2, A3, B0, B1)                            \
    asm volatile(                                                      \
        "mma.sync.aligned.m16n8k8.row.col.f32.tf32.tf32.f32 "          \
        "{%0,%1,%2,%3}, {%4,%5,%6,%7}, {%8,%9}, {%0,%1,%2,%3};"        \
        : "+f"((D)[0]), "+f"((D)[1]), "+f"((D)[2]), "+f"((D)[3])       \
        : "r"(A0), "r"(A1), "r"(A2), "r"(A3), "r"(B0), "r"(B1))

// =====================================================================
// Producer routine: 128 threads (warps 8-11) build x_proj for group P
// into ring buffer `rbuf`. Stage x (LDG->tf32->Ast), bar, W_ih GEMM on
// tensor pipe, epilogue adds bias and stores [tl][gate] float2 pairs.
// =====================================================================
__device__ __forceinline__ void produce_group(
    const float* __restrict__ x, const unsigned* __restrict__ Wst,
    unsigned* __restrict__ Ast, float* __restrict__ rbuf,
    const float* __restrict__ bias_s, int P, int tid2, int b0g)
{
    // ---- stage x: 16 rows x 128 k; thread = (row, 16-float seg) ----
    {
        const int row = tid2 >> 3;          // 0..15  (b*8 + tl)
        const int seg = tid2 & 7;           // k = seg*16
        const int b   = row >> 3, tl = row & 7;
        const float* src = &x[(((size_t)(b0g + b)) * T_SEQ + (size_t)P * 8 + tl) * ISZ + seg * 16];
        float4 v0 = *(const float4*)&src[0];
        float4 v1 = *(const float4*)&src[4];
        float4 v2 = *(const float4*)&src[8];
        float4 v3 = *(const float4*)&src[12];
        unsigned* dst = &Ast[row * WPITCH + seg * 16];
        dst[0]  = f2tf32(v0.x); dst[1]  = f2tf32(v0.y); dst[2]  = f2tf32(v0.z); dst[3]  = f2tf32(v0.w);
        dst[4]  = f2tf32(v1.x); dst[5]  = f2tf32(v1.y); dst[6]  = f2tf32(v1.z); dst[7]  = f2tf32(v1.w);
        dst[8]  = f2tf32(v2.x); dst[9]  = f2tf32(v2.y); dst[10] = f2tf32(v2.z); dst[11] = f2tf32(v2.w);
        dst[12] = f2tf32(v3.x); dst[13] = f2tf32(v3.y); dst[14] = f2tf32(v3.z); dst[15] = f2tf32(v3.w);
    }
    BAR_PROD();

    // ---- W_ih GEMM: 4 warps x 64 gate-cols each, 8 n-tiles ----
    const int pw   = tid2 >> 5;             // producer warp 0..3
    const int lane = tid2 & 31;
    const int gid  = lane >> 2, tig = lane & 3;

    float acc[8][4];
    #pragma unroll
    for (int n = 0; n < 8; n++)
        #pragma unroll
        for (int i = 0; i < 4; i++) acc[n][i] = 0.f;

    #pragma unroll
    for (int ks = 0; ks < 16; ++ks) {
        const int k0 = ks * 8;
        unsigned a0 = Ast[ gid      * WPITCH + k0 + tig];
        unsigned a1 = Ast[(gid + 8) * WPITCH + k0 + tig];
        unsigned a2 = Ast[ gid      * WPITCH + k0 + tig + 4];
        unsigned a3 = Ast[(gid + 8) * WPITCH + k0 + tig + 4];
        #pragma unroll
        for (int nt = 0; nt < 8; nt++) {
            const int nl = pw * 64 + nt * 8 + gid;
            unsigned bb0 = Wst[nl * WPITCH + k0 + tig];
            unsigned bb1 = Wst[nl * WPITCH + k0 + tig + 4];
            MMA_TF32(acc[nt], a0, a1, a2, a3, bb0, bb1);
        }
    }
    // epilogue: rows gid->(b0,tl=gid), gid+8->(b1,tl=gid); cols 2tig,2tig+1
    #pragma unroll
    for (int nt = 0; nt < 8; nt++) {
        const int nl2 = pw * 64 + nt * 8 + 2 * tig;
        const float bs0 = bias_s[nl2], bs1 = bias_s[nl2 + 1];
        float* r0 = &rbuf[(gid * RPITCH + nl2) * 2];
        r0[0] = acc[nt][0] + bs0;     // (b0, col nl2)
        r0[2] = acc[nt][1] + bs1;     // (b0, col nl2+1)
        r0[1] = acc[nt][2] + bs0;     // (b1, col nl2)
        r0[3] = acc[nt][3] + bs1;     // (b1, col nl2+1)
    }
}

// =====================================================================
// FUSED warp-specialized kernel: 128 CTAs (one batch pair), 384 threads.
// Warps 0-7: R11-proven FFMA2 recurrence consuming the SMEM ring.
// Warps 8-11: produce group P+1's x_proj on the tensor pipe, overlapped
// with the 8 steps of group P (double-buffered ring).
// =====================================================================
__global__ __launch_bounds__(NTHR, 1) void lstm_fused_kernel(
    const float* __restrict__ x, const float* __restrict__ W_ih,
    const float* __restrict__ W_hh,
    const float* __restrict__ b_ih, const float* __restrict__ b_hh)
{
    extern __shared__ __align__(16) unsigned smem_raw[];
    unsigned* Wst  = smem_raw;                        // 256*132 tf32 words
    unsigned* Ast  = Wst + GSZ * WPITCH;              // 16*132 tf32 words
    float*    ring = (float*)(Ast + 16 * WPITCH);     // 2 bufs * 8 * RPITCH * 2
    float*    bias_s = ring + 2 * 8 * RPITCH * 2;     // 256
    ull*      h_s  = (ull*)(bias_s + GSZ);            // 64
    ull*      gate_s = h_s + HSZ;                     // 256

    const int tid = threadIdx.x;
    const int bp  = blockIdx.x;
    const int b0g = bp * 2;

    // ---- stage W_ih -> SMEM tf32 (all 384 threads) ----
    for (int i = tid; i < GSZ * (ISZ / 4); i += NTHR) {
        int gg = i >> 5, s = i & 31;
        float4 v = ((const float4*)W_ih)[(size_t)gg * 32 + s];
        unsigned* dst = &Wst[gg * WPITCH + s * 4];
        dst[0] = f2tf32(v.x); dst[1] = f2tf32(v.y);
        dst[2] = f2tf32(v.z); dst[3] = f2tf32(v.w);
    }
    if (tid < GSZ) bias_s[tid] = b_ih[tid] + b_hh[tid];
    if (tid < HSZ) h_s[tid] = 0ull;
    __syncthreads();

    if (tid >= 256) {
        // ================= PRODUCER WARPS =================
        const int tid2 = tid - 256;
        produce_group(x, Wst, Ast, ring, bias_s, 0, tid2, b0g);   // group 0 -> buf 0
        __syncthreads();
        for (int P = 0; P < NGRP; ++P) {
            if (P + 1 < NGRP)
                produce_group(x, Wst, Ast, ring + ((P + 1) & 1) * (8 * RPITCH * 2),
                              bias_s, P + 1, tid2, b0g);
            __syncthreads();
        }
    } else {
        // ================= CONSUMER WARPS =================
        const int g   = tid;
        const int j   = g & 63;
        const int sec = g >> 6;       // 0:i 1:f 2:g 3:o (warp-uniform)
        const float kmul = (sec == 2) ? 2.8853900817779268f : 1.4426950408889634f;
        const float aco  = (sec == 2) ?  2.0f : 1.0f;
        const float bco  = (sec == 2) ? -1.0f : 0.0f;

        // W_hh row g duplicated into f32x2 pairs (128 regs)
        ull w2[HSZ];
        {
            const float4* wrow = (const float4*)&W_hh[g * HSZ];
            #pragma unroll
            for (int q = 0; q < 16; ++q) {
                float4 w = wrow[q];
                w2[q * 4 + 0] = pack2(w.x, w.x);
                w2[q * 4 + 1] = pack2(w.y, w.y);
                w2[q * 4 + 2] = pack2(w.z, w.z);
                w2[q * 4 + 3] = pack2(w.w, w.w);
            }
        }
        float c0 = 0.f, c1 = 0.f;
        __syncthreads();              // matches producer's post-group0 barrier

        for (int P = 0; P < NGRP; ++P) {
            const float* rbuf = ring + (P & 1) * (8 * RPITCH * 2);
            for (int tl = 0; tl < 8; ++tl) {
                ull xp = *(const ull*)&rbuf[(tl * RPITCH + g) * 2];

                ull acc0 = 0ull, acc1 = 0ull, acc2 = 0ull, acc3 = 0ull;
                const ulonglong2* h2 = (const ulonglong2*)h_s;
                #pragma unroll
                for (int kk = 0; kk < 16; ++kk) {
                    ulonglong2 ha = h2[2 * kk];
                    ulonglong2 hb = h2[2 * kk + 1];
                    acc0 = ffma2(w2[4 * kk + 0], ha.x, acc0);
                    acc1 = ffma2(w2[4 * kk + 1], ha.y, acc1);
                    acc2 = ffma2(w2[4 * kk + 2], hb.x, acc2);
                    acc3 = ffma2(w2[4 * kk + 3], hb.y, acc3);
                }
                ull gsum = fadd2(fadd2(acc0, acc1), fadd2(acc2, acc3));
                gsum = fadd2(gsum, xp);   // bias folded into ring by producer

                float2 gv = unpack2(gsum);
                float r0 = fmaf(aco, rcp_ap(1.0f + ex2_ap(-kmul * gv.x)), bco);
                float r1 = fmaf(aco, rcp_ap(1.0f + ex2_ap(-kmul * gv.y)), bco);
                gate_s[g] = pack2(r0, r1);
                BAR_CONS();

                if (g < HSZ) {
                    float2 iv = unpack2(gate_s[j]);
                    float2 fv = unpack2(gate_s[64 + j]);
                    float2 gg = unpack2(gate_s[128 + j]);
                    float2 ov = unpack2(gate_s[192 + j]);
                    c0 = fmaf(fv.x, c0, iv.x * gg.x);
                    c1 = fmaf(fv.y, c1, iv.y * gg.y);
                    float h0 = ov.x * tanh_f(c0);
                    float h1 = ov.y * tanh_f(c1);
                    ull hp = pack2(h0, h1);
                    h_s[j] = hp;
                    if (P == NGRP - 1 && tl == 7) g_hT[bp * HSZ + j] = hp;
                }
                BAR_CONS();
            }
            __syncthreads();          // group boundary: swap ring buffers
        }
    }
}

// =====================================================================
// Kernel C: logits = h_T @ W_cls^T + b_cls   (256 x 10)
// =====================================================================
__global__ void cls_kernel(const float* __restrict__ W_cls,
                           const float* __restrict__ b_cls,
                           float* __restrict__ out)
{
    const int b = blockIdx.x, lane = threadIdx.x;
    const int bp = b >> 1, par = b & 1;
    float2 p0 = unpack2(g_hT[bp * HSZ + lane]);
    float2 p1 = unpack2(g_hT[bp * HSZ + lane + 32]);
    float h0 = par ? p0.y : p0.x;
    float h1 = par ? p1.y : p1.x;
    #pragma unroll
    for (int c = 0; c < NCLS; ++c) {
        float p = h0 * W_cls[c * HSZ + lane] + h1 * W_cls[c * HSZ + lane + 32];
        #pragma unroll
        for (int off = 16; off; off >>= 1)
            p += __shfl_xor_sync(0xffffffffu, p, off);
        if (lane == 0) out[b * NCLS + c] = p + b_cls[c];
    }
}

// =====================================================================
static const int SMEM_BYTES =
    (GSZ * WPITCH + 16 * WPITCH) * 4 +      // Wst + Ast
    2 * 8 * RPITCH * 2 * 4 +                 // double-buffered ring
    GSZ * 4 +                                // bias_s
    (HSZ + GSZ) * 8;                         // h_s + gate_s

extern "C" void kernel_launch(void* const* d_in, const int* in_sizes, int n_in,
                              void* d_out, int out_size) {
    const float* x     = (const float*)d_in[0];
    const float* W_ih  = (const float*)d_in[1];
    const float* W_hh  = (const float*)d_in[2];
    const float* b_ih  = (const float*)d_in[3];
    const float* b_hh  = (const float*)d_in[4];
    const float* W_cls = (const float*)d_in[5];
    const float* b_cls = (const float*)d_in[6];
    float* out = (float*)d_out;

    cudaFuncSetAttribute(lstm_fused_kernel,
                         cudaFuncAttributeMaxDynamicSharedMemorySize, SMEM_BYTES);
    lstm_fused_kernel<<<NBP, NTHR, SMEM_BYTES>>>(x, W_ih, W_hh, b_ih, b_hh);
    cls_kernel<<<BATCH, 32>>>(W_cls, b_cls, out);
}